// round 13
// baseline (speedup 1.0000x reference)
#include <cuda_runtime.h>
#include <math.h>
#include <stdint.h>

// Problem constants (fixed by the dataset instance)
#define M_TOK 16384   // B*S = 4*4096
#define DDIM  1024    // model dim = H*Khead = 16*64
// windows: 8 of 512 tokens; heads: 16 of 64

// Static device scratch (allocation-free rule): 3 x 64MB
__device__ float g_Q[(size_t)M_TOK * DDIM];
__device__ float g_K[(size_t)M_TOK * DDIM];
__device__ float g_V[(size_t)M_TOK * DDIM];

// Raw fp32 fed to tf32 MMA == truncation to tf32.
__device__ __forceinline__ void mma_tf32(
    float& d0, float& d1, float& d2, float& d3,
    uint32_t a0, uint32_t a1, uint32_t a2, uint32_t a3,
    uint32_t b0, uint32_t b1)
{
    asm volatile(
        "mma.sync.aligned.m16n8k8.row.col.f32.tf32.tf32.f32 "
        "{%0,%1,%2,%3}, {%4,%5,%6,%7}, {%8,%9}, {%0,%1,%2,%3};"
        : "+f"(d0), "+f"(d1), "+f"(d2), "+f"(d3)
        : "r"(a0), "r"(a1), "r"(a2), "r"(a3), "r"(b0), "r"(b1));
}

// ldmatrix.x4.b16 over tf32 data: each 8x8-b16 tile == 8row x 4col b32 tile,
// lane L -> elem[L>>2][L&3] == the m16n8k8 tf32 fragment mapping.
__device__ __forceinline__ void ldsm4(uint32_t* r, const float* p) {
    uint32_t a = (uint32_t)__cvta_generic_to_shared(p);
    asm volatile("ldmatrix.sync.aligned.m8n8.x4.shared.b16 {%0,%1,%2,%3}, [%4];"
                 : "=r"(r[0]), "=r"(r[1]), "=r"(r[2]), "=r"(r[3]) : "r"(a));
}

__device__ __forceinline__ void cp_async16(void* smem_dst, const void* gsrc) {
    uint32_t s = (uint32_t)__cvta_generic_to_shared(smem_dst);
    asm volatile("cp.async.cg.shared.global [%0], [%1], 16;" :: "r"(s), "l"(gsrc));
}
__device__ __forceinline__ void cp_commit() {
    asm volatile("cp.async.commit_group;");
}
__device__ __forceinline__ void cp_wait_all() {
    asm volatile("cp.async.wait_group 0;");
}

// ---------------------------------------------------------------------------
// TF32 tensor-core GEMM, 3-output variant (z selects Bm/bias/C).
// 128x128x32 block tile, 256 threads = 8 warps (4 m x 2 n).
// 2-stage cp.async pipeline (R8 structure — measured best).
// A-fragments via ldmatrix.x4; B-fragments scalar ([k][n] layout).
// dyn smem: 2*(128*36 + 32*136)*4 = 71680 B
// ---------------------------------------------------------------------------
#define GEMM_SMEM_BYTES ((2 * 128 * 36 + 2 * 32 * 136) * 4)

__global__ __launch_bounds__(256) void tf32_gemm3_kernel(
    const float* __restrict__ A,
    const float* __restrict__ B0, const float* __restrict__ B1,
    const float* __restrict__ B2,
    const float* __restrict__ bias0, const float* __restrict__ bias1,
    const float* __restrict__ bias2,
    const float* __restrict__ resid,
    float* __restrict__ C0, float* __restrict__ C1, float* __restrict__ C2)
{
    extern __shared__ float gsm[];
    float (*As)[128][36] = (float(*)[128][36])gsm;               // [2][128][36]
    float (*Bs)[32][136] = (float(*)[32][136])(gsm + 2 * 128 * 36);

    int z = blockIdx.z;
    const float* Bm   = (z == 0) ? B0 : (z == 1) ? B1 : B2;
    const float* bias = (z == 0) ? bias0 : (z == 1) ? bias1 : bias2;
    float* C          = (z == 0) ? C0 : (z == 1) ? C1 : C2;

    int tid = threadIdx.x;
    int lane = tid & 31, wid = tid >> 5;
    int warp_m = wid & 3;
    int warp_n = wid >> 2;
    int gid = lane >> 2, tig = lane & 3;

    int row0 = blockIdx.y << 7;
    int col0 = blockIdx.x << 7;

    // ldmatrix lane address components for A fragments:
    // tile t = lane>>3: row += (t&1)*8, col += (t>>1)*4
    int lmRow = ((lane >> 3) & 1) << 3 | (lane & 7);   // (t&1)*8 + (lane&7)
    int lmCol = (lane >> 4) << 2;                      // (t>>1)*4

    float acc[2][8][4];
#pragma unroll
    for (int mt = 0; mt < 2; mt++)
#pragma unroll
        for (int nt = 0; nt < 8; nt++)
#pragma unroll
            for (int r = 0; r < 4; r++) acc[mt][nt][r] = 0.f;

    int rowA = tid >> 1;
    int colA0 = (tid & 1) << 4;        // 0 or 16 floats
    int rowB = tid >> 3;
    int colB0 = (tid & 7) << 4;        // 0..112 step 16

    const float* Ag = A + (size_t)(row0 + rowA) * DDIM + colA0;
    const float* Bg = Bm + (size_t)rowB * DDIM + col0 + colB0;

    // preamble: stage tile 0
#pragma unroll
    for (int p = 0; p < 4; p++) {
        cp_async16(&As[0][rowA][colA0 + p * 4], Ag + p * 4);
        cp_async16(&Bs[0][rowB][colB0 + p * 4], Bg + p * 4);
    }
    cp_commit();
    cp_wait_all();
    __syncthreads();

    for (int t = 0; t < 32; t++) {
        if (t < 31) {
            int sn = (t + 1) & 1;
            int k0n = (t + 1) << 5;
#pragma unroll
            for (int p = 0; p < 4; p++) {
                cp_async16(&As[sn][rowA][colA0 + p * 4], Ag + k0n + p * 4);
                cp_async16(&Bs[sn][rowB][colB0 + p * 4],
                           Bg + (size_t)k0n * DDIM + p * 4);
            }
            cp_commit();
        }

        int s = t & 1;
#pragma unroll
        for (int ks = 0; ks < 4; ks++) {
            int kk = ks << 3;
            uint32_t af[2][4];
#pragma unroll
            for (int mt = 0; mt < 2; mt++) {
                int r = (warp_m << 5) + (mt << 4) + lmRow;
                ldsm4(af[mt], &As[s][r][kk + lmCol]);
            }
            uint32_t bf[8][2];
            int nbase = (warp_n << 6) + gid;
#pragma unroll
            for (int nt = 0; nt < 8; nt++) {
                int c = nbase + (nt << 3);
                bf[nt][0] = __float_as_uint(Bs[s][kk + tig][c]);
                bf[nt][1] = __float_as_uint(Bs[s][kk + tig + 4][c]);
            }
#pragma unroll
            for (int mt = 0; mt < 2; mt++)
#pragma unroll
                for (int nt = 0; nt < 8; nt++)
                    mma_tf32(acc[mt][nt][0], acc[mt][nt][1],
                             acc[mt][nt][2], acc[mt][nt][3],
                             af[mt][0], af[mt][1], af[mt][2], af[mt][3],
                             bf[nt][0], bf[nt][1]);
        }
        cp_wait_all();
        __syncthreads();
    }

#pragma unroll
    for (int mt = 0; mt < 2; mt++) {
#pragma unroll
        for (int nt = 0; nt < 8; nt++) {
            int col = col0 + (warp_n << 6) + (nt << 3) + (tig << 1);
            float bx = bias[col], by = bias[col + 1];
#pragma unroll
            for (int h = 0; h < 2; h++) {
                size_t row = (size_t)row0 + (warp_m << 5) + (mt << 4) + gid + (h << 3);
                float2 o;
                o.x = acc[mt][nt][2 * h + 0] + bx;
                o.y = acc[mt][nt][2 * h + 1] + by;
                if (resid) {
                    float2 rv = *(const float2*)(resid + row * DDIM + col);
                    o.x += rv.x; o.y += rv.y;
                }
                *(float2*)(C + row * DDIM + col) = o;
            }
        }
    }
}

// ---------------------------------------------------------------------------
// Tensor-core windowed attention, 32 q-rows per block, 2 CTAs/SM.
// 512 threads = 16 warps: warp w -> n-tile (w&7), m-tile mg=(w>>3).
// ldmatrix for Q A-frags, QK B-frags (KV is [n][k] layout), PV A-frags
// (Ssm is [m][k]); PV B stays scalar ([k][n] layout).
// Smem: Ssm[32][516] + KV[2][64][68] = 100864 B.
// ---------------------------------------------------------------------------
#define SS_LD 516
#define QK_LD 68
#define ATTN_SMEM_BYTES ((32 * SS_LD + 2 * 64 * QK_LD) * 4)

__global__ __launch_bounds__(512, 2) void attn_mma_kernel(
    const float* __restrict__ Km, const float* __restrict__ V,
    float* __restrict__ QC)   // Q in, context out (in-place)
{
    extern __shared__ float sm[];
    float* Ssm = sm;                        // [32][516]
    float* KV0 = sm + 32 * SS_LD;           // [64][68] stage 0
    float* KV1 = KV0 + 64 * QK_LD;          // [64][68] stage 1 (Q overlay)

    int tid = threadIdx.x;
    int lane = tid & 31;
    int w = tid >> 5;
    int gid = lane >> 2, tig = lane & 3;
    int nt = w & 7;
    int mg = w >> 3;                        // 0..1
    int mrow = mg << 4;

    // ldmatrix lane addressing:
    // A-style (4 tiles r0/k0, r8/k0, r0/k4, r8/k4):
    int lmRowA = ((lane >> 3) & 1) << 3 | (lane & 7);
    int lmColA = (lane >> 4) << 2;
    // B-style for QK (4 tiles: cols +0,+4,+8,+12; rows nt*8..+7):
    int lmRowB = (nt << 3) + (lane & 7);
    int lmColB = (lane >> 3) << 2;          // 0,4,8,12

    int hid = blockIdx.y;                   // (b, win, h)
    int b = hid >> 7;
    int wn = (hid >> 4) & 7;
    int h = hid & 15;
    int t0 = b * 4096 + wn * 512;
    int hcol = h << 6;
    int qbase = blockIdx.x << 5;            // 32 q-rows per block

    int r = tid >> 3;                       // 0..63 KV staging row
    int c0 = (tid & 7) << 3;                // 0..56 staging col (8 floats)

    // ---- stage Q (32x64) into KV1 + prefetch K tile 0 into KV0 ----
    {
        int qr = tid >> 4;                  // 0..31
        int qc = (tid & 15) << 2;           // 0..60
        float4 qv = *(const float4*)(QC + (size_t)(t0 + qbase + qr) * DDIM + hcol + qc);
        const float* ksrc = Km + (size_t)(t0 + r) * DDIM + hcol + c0;
        cp_async16(&KV0[r * QK_LD + c0], ksrc);
        cp_async16(&KV0[r * QK_LD + c0 + 4], ksrc + 4);
        cp_commit();
        *(float4*)&KV1[qr * QK_LD + qc] = qv;
    }
    __syncthreads();                        // Q visible

    // ---- hoist Q A-fragments from KV1 via ldmatrix ----
    uint32_t af[8][4];
#pragma unroll
    for (int ks = 0; ks < 8; ks++)
        ldsm4(af[ks], &KV1[(mrow + lmRowA) * QK_LD + (ks << 3) + lmColA]);
    cp_wait_all();
    __syncthreads();                        // af done (KV1 free), K0 visible

    // ---- scores S[32][512] = Q K^T via mma, pipelined over 8 key tiles ----
    for (int kt = 0; kt < 8; kt++) {
        float* cur = (kt & 1) ? KV1 : KV0;
        if (kt < 7) {
            float* nxt = (kt & 1) ? KV0 : KV1;
            const float* src = Km + (size_t)(t0 + (kt + 1) * 64 + r) * DDIM + hcol + c0;
            cp_async16(&nxt[r * QK_LD + c0], src);
            cp_async16(&nxt[r * QK_LD + c0 + 4], src + 4);
            cp_commit();
        }
        float s0 = 0.f, s1 = 0.f, s2 = 0.f, s3 = 0.f;
#pragma unroll
        for (int ks2 = 0; ks2 < 4; ks2++) {
            uint32_t bb[4];   // b0/b1 for ks=2*ks2, b0/b1 for ks=2*ks2+1
            ldsm4(bb, &cur[lmRowB * QK_LD + (ks2 << 4) + lmColB]);
            mma_tf32(s0, s1, s2, s3,
                     af[2 * ks2][0], af[2 * ks2][1], af[2 * ks2][2], af[2 * ks2][3],
                     bb[0], bb[1]);
            mma_tf32(s0, s1, s2, s3,
                     af[2 * ks2 + 1][0], af[2 * ks2 + 1][1],
                     af[2 * ks2 + 1][2], af[2 * ks2 + 1][3],
                     bb[2], bb[3]);
        }
        {
            int row = mrow + gid;
            int col = kt * 64 + (nt << 3) + (tig << 1);
            *(float2*)&Ssm[row * SS_LD + col] = make_float2(s0, s1);
            *(float2*)&Ssm[(row + 8) * SS_LD + col] = make_float2(s2, s3);
        }
        cp_wait_all();
        __syncthreads();
    }

    // prefetch V tile 0 into KV0 (both buffers free), overlaps softmax
    {
        const float* src = V + (size_t)(t0 + r) * DDIM + hcol + c0;
        cp_async16(&KV0[r * QK_LD + c0], src);
        cp_async16(&KV0[r * QK_LD + c0 + 4], src + 4);
        cp_commit();
    }

    // ---- softmax over 512 keys per row (2 rows per warp), scale 0.125 ----
    {
#pragma unroll
        for (int q = 0; q < 2; q++) {
            int rr = (w << 1) + q;
            float vals[16];
            float m = -1e30f;
#pragma unroll
            for (int t = 0; t < 16; t++) {
                vals[t] = Ssm[rr * SS_LD + lane + 32 * t];
                m = fmaxf(m, vals[t]);
            }
#pragma unroll
            for (int off = 16; off > 0; off >>= 1)
                m = fmaxf(m, __shfl_xor_sync(0xffffffffu, m, off));
            float s = 0.f;
#pragma unroll
            for (int t = 0; t < 16; t++) {
                float e = __expf((vals[t] - m) * 0.125f);
                vals[t] = e;
                s += e;
            }
#pragma unroll
            for (int off = 16; off > 0; off >>= 1)
                s += __shfl_xor_sync(0xffffffffu, s, off);
            float inv = 1.0f / s;
#pragma unroll
            for (int t = 0; t < 16; t++)
                Ssm[rr * SS_LD + lane + 32 * t] = vals[t] * inv;
        }
    }
    cp_wait_all();
    __syncthreads();   // V0 ready; softmax writes visible

    // ---- O[32][64] = P[32][512] @ V[512][64], pipelined ----
    float o0 = 0.f, o1 = 0.f, o2 = 0.f, o3 = 0.f;

    for (int kt = 0; kt < 8; kt++) {
        float* cur = (kt & 1) ? KV1 : KV0;
        if (kt < 7) {
            float* nxt = (kt & 1) ? KV0 : KV1;
            const float* src = V + (size_t)(t0 + (kt + 1) * 64 + r) * DDIM + hcol + c0;
            cp_async16(&nxt[r * QK_LD + c0], src);
            cp_async16(&nxt[r * QK_LD + c0 + 4], src + 4);
            cp_commit();
        }
#pragma unroll
        for (int ks = 0; ks < 8; ks++) {
            int kk = ks << 3;
            uint32_t b0 = __float_as_uint(cur[(kk + tig) * QK_LD + (nt << 3) + gid]);
            uint32_t b1 = __float_as_uint(cur[(kk + tig + 4) * QK_LD + (nt << 3) + gid]);
            uint32_t aa[4];
            ldsm4(aa, &Ssm[(mrow + lmRowA) * SS_LD + kt * 64 + kk + lmColA]);
            mma_tf32(o0, o1, o2, o3, aa[0], aa[1], aa[2], aa[3], b0, b1);
        }
        cp_wait_all();
        __syncthreads();
    }

    // ---- store context in-place over Q ----
    {
        size_t row = (size_t)t0 + qbase + mrow + gid;
        int col = hcol + (nt << 3) + (tig << 1);
        *(float2*)(QC + row * DDIM + col) = make_float2(o0, o1);
        *(float2*)(QC + (row + 8) * DDIM + col) = make_float2(o2, o3);
    }
}

// ---------------------------------------------------------------------------
// LayerNorm per row (1024 elems), keras eps = 1e-3. One block per row.
// ---------------------------------------------------------------------------
__global__ __launch_bounds__(256) void ln_kernel(
    const float* __restrict__ Y, const float* __restrict__ gamma,
    const float* __restrict__ beta, float* __restrict__ out)
{
    int row = blockIdx.x;
    int tid = threadIdx.x;
    const float* y = Y + (size_t)row * DDIM;

    float4 v = *(const float4*)(y + tid * 4);
    float s  = v.x + v.y + v.z + v.w;
    float sq = v.x * v.x + v.y * v.y + v.z * v.z + v.w * v.w;

#pragma unroll
    for (int off = 16; off > 0; off >>= 1) {
        s  += __shfl_xor_sync(0xffffffffu, s, off);
        sq += __shfl_xor_sync(0xffffffffu, sq, off);
    }
    __shared__ float ss[8], ssq[8];
    int lane = tid & 31, wid = tid >> 5;
    if (lane == 0) { ss[wid] = s; ssq[wid] = sq; }
    __syncthreads();
    float S = 0.f, SQ = 0.f;
#pragma unroll
    for (int i = 0; i < 8; i++) { S += ss[i]; SQ += ssq[i]; }

    float mu  = S * (1.0f / 1024.0f);
    float var = SQ * (1.0f / 1024.0f) - mu * mu;
    float inv = rsqrtf(var + 1e-3f);

    float4 g  = *(const float4*)(gamma + tid * 4);
    float4 be = *(const float4*)(beta + tid * 4);
    float4 o;
    o.x = (v.x - mu) * inv * g.x + be.x;
    o.y = (v.y - mu) * inv * g.y + be.y;
    o.z = (v.z - mu) * inv * g.z + be.z;
    o.w = (v.w - mu) * inv * g.w + be.w;
    *(float4*)(out + (size_t)row * DDIM + tid * 4) = o;
}

// ---------------------------------------------------------------------------
extern "C" void kernel_launch(void* const* d_in, const int* in_sizes, int n_in,
                              void* d_out, int out_size)
{
    const float* x     = (const float*)d_in[0];
    const float* Wq    = (const float*)d_in[1];
    const float* bq    = (const float*)d_in[2];
    const float* Wk    = (const float*)d_in[3];
    const float* bk    = (const float*)d_in[4];
    const float* Wv    = (const float*)d_in[5];
    const float* bv    = (const float*)d_in[6];
    const float* Wo    = (const float*)d_in[7];
    const float* bo    = (const float*)d_in[8];
    const float* gamma = (const float*)d_in[9];
    const float* beta  = (const float*)d_in[10];
    float* out = (float*)d_out;
    (void)in_sizes; (void)n_in; (void)out_size;

    float *Qp, *Kp, *Vp;
    cudaGetSymbolAddress((void**)&Qp, g_Q);
    cudaGetSymbolAddress((void**)&Kp, g_K);
    cudaGetSymbolAddress((void**)&Vp, g_V);

    cudaFuncSetAttribute(tf32_gemm3_kernel,
                         cudaFuncAttributeMaxDynamicSharedMemorySize, GEMM_SMEM_BYTES);
    cudaFuncSetAttribute(attn_mma_kernel,
                         cudaFuncAttributeMaxDynamicSharedMemorySize, ATTN_SMEM_BYTES);

    // Q, K, V in one launch: z selects weights/bias/output
    tf32_gemm3_kernel<<<dim3(8, 128, 3), 256, GEMM_SMEM_BYTES>>>(
        x, Wq, Wk, Wv, bq, bk, bv, nullptr, Qp, Kp, Vp);

    // ctx overwrites Q in-place; grid: 16 q-tiles of 32 x 512 heads
    attn_mma_kernel<<<dim3(16, 512), 512, ATTN_SMEM_BYTES>>>(Kp, Vp, Qp);

    // Y = ctx @ Wo + bo + x   (write Y into g_K, dead after attention)
    tf32_gemm3_kernel<<<dim3(8, 128, 1), 256, GEMM_SMEM_BYTES>>>(
        Qp, Wo, Wo, Wo, bo, bo, bo, x, Kp, Kp, Kp);

    ln_kernel<<<M_TOK, 256>>>(Kp, gamma, beta, out);
}

// round 14
// speedup vs baseline: 1.4039x; 1.4039x over previous
#include <cuda_runtime.h>
#include <math.h>
#include <stdint.h>

// Problem constants (fixed by the dataset instance)
#define M_TOK 16384   // B*S = 4*4096
#define DDIM  1024    // model dim = H*Khead = 16*64
// windows: 8 of 512 tokens; heads: 16 of dim 64

// Static device scratch (allocation-free rule): 3 x 64MB
__device__ float g_Q[(size_t)M_TOK * DDIM];
__device__ float g_K[(size_t)M_TOK * DDIM];
__device__ float g_V[(size_t)M_TOK * DDIM];

// Raw fp32 fed to tf32 MMA == truncation to tf32.
__device__ __forceinline__ void mma_tf32(
    float& d0, float& d1, float& d2, float& d3,
    uint32_t a0, uint32_t a1, uint32_t a2, uint32_t a3,
    uint32_t b0, uint32_t b1)
{
    asm volatile(
        "mma.sync.aligned.m16n8k8.row.col.f32.tf32.tf32.f32 "
        "{%0,%1,%2,%3}, {%4,%5,%6,%7}, {%8,%9}, {%0,%1,%2,%3};"
        : "+f"(d0), "+f"(d1), "+f"(d2), "+f"(d3)
        : "r"(a0), "r"(a1), "r"(a2), "r"(a3), "r"(b0), "r"(b1));
}

__device__ __forceinline__ void cp_async16(void* smem_dst, const void* gsrc) {
    uint32_t s = (uint32_t)__cvta_generic_to_shared(smem_dst);
    asm volatile("cp.async.cg.shared.global [%0], [%1], 16;" :: "r"(s), "l"(gsrc));
}
__device__ __forceinline__ void cp_commit() {
    asm volatile("cp.async.commit_group;");
}
__device__ __forceinline__ void cp_wait_all() {
    asm volatile("cp.async.wait_group 0;");
}

// ---------------------------------------------------------------------------
// TF32 tensor-core GEMM, 3-output variant (z selects Bm/bias/C).
// 256x128x32 block tile, 256 threads = 8 warps (4 m x 2 n), warp 64x64.
// Raised arithmetic intensity (16 MAC/LDS-byte vs 5.3) — the GEMM was
// measured LDS-throughput-bound, not latency-bound.
// 2-stage cp.async pipeline (R8 structure — measured best).
// dyn smem: 2*(256*36 + 32*136)*4 = 108544 B
// ---------------------------------------------------------------------------
#define GEMM_SMEM_BYTES ((2 * 256 * 36 + 2 * 32 * 136) * 4)

__global__ __launch_bounds__(256) void tf32_gemm3_kernel(
    const float* __restrict__ A,
    const float* __restrict__ B0, const float* __restrict__ B1,
    const float* __restrict__ B2,
    const float* __restrict__ bias0, const float* __restrict__ bias1,
    const float* __restrict__ bias2,
    const float* __restrict__ resid,
    float* __restrict__ C0, float* __restrict__ C1, float* __restrict__ C2)
{
    extern __shared__ float gsm[];
    float (*As)[256][36] = (float(*)[256][36])gsm;               // [2][256][36]
    float (*Bs)[32][136] = (float(*)[32][136])(gsm + 2 * 256 * 36);

    int z = blockIdx.z;
    const float* Bm   = (z == 0) ? B0 : (z == 1) ? B1 : B2;
    const float* bias = (z == 0) ? bias0 : (z == 1) ? bias1 : bias2;
    float* C          = (z == 0) ? C0 : (z == 1) ? C1 : C2;

    int tid = threadIdx.x;
    int lane = tid & 31, wid = tid >> 5;
    int warp_m = wid & 3;              // 4 warps over M: 64 rows each
    int warp_n = wid >> 2;             // 2 warps over N: 64 cols each
    int gid = lane >> 2, tig = lane & 3;

    int row0 = blockIdx.y << 8;        // 256 rows per block
    int col0 = blockIdx.x << 7;

    float acc[4][8][4];                // [mt 16][nt 8][c-regs]
#pragma unroll
    for (int mt = 0; mt < 4; mt++)
#pragma unroll
        for (int nt = 0; nt < 8; nt++)
#pragma unroll
            for (int r = 0; r < 4; r++) acc[mt][nt][r] = 0.f;

    int rowA = tid >> 1;               // 0..127 (stages rowA and rowA+128)
    int colA0 = (tid & 1) << 4;        // 0 or 16 floats
    int rowB = tid >> 3;
    int colB0 = (tid & 7) << 4;        // 0..112 step 16

    const float* Ag = A + (size_t)(row0 + rowA) * DDIM + colA0;
    const float* Ag2 = Ag + (size_t)128 * DDIM;
    const float* Bg = Bm + (size_t)rowB * DDIM + col0 + colB0;

    // preamble: stage tile 0
#pragma unroll
    for (int p = 0; p < 4; p++) {
        cp_async16(&As[0][rowA][colA0 + p * 4], Ag + p * 4);
        cp_async16(&As[0][rowA + 128][colA0 + p * 4], Ag2 + p * 4);
        cp_async16(&Bs[0][rowB][colB0 + p * 4], Bg + p * 4);
    }
    cp_commit();
    cp_wait_all();
    __syncthreads();

    for (int t = 0; t < 32; t++) {
        if (t < 31) {
            int sn = (t + 1) & 1;
            int k0n = (t + 1) << 5;
#pragma unroll
            for (int p = 0; p < 4; p++) {
                cp_async16(&As[sn][rowA][colA0 + p * 4], Ag + k0n + p * 4);
                cp_async16(&As[sn][rowA + 128][colA0 + p * 4], Ag2 + k0n + p * 4);
                cp_async16(&Bs[sn][rowB][colB0 + p * 4],
                           Bg + (size_t)k0n * DDIM + p * 4);
            }
            cp_commit();
        }

        int s = t & 1;
#pragma unroll
        for (int ks = 0; ks < 4; ks++) {
            int kk = ks << 3;
            uint32_t af[4][4];
            int mrow = (warp_m << 6) + gid;
#pragma unroll
            for (int mt = 0; mt < 4; mt++) {
                int r = mrow + (mt << 4);
                af[mt][0] = __float_as_uint(As[s][r][kk + tig]);
                af[mt][1] = __float_as_uint(As[s][r + 8][kk + tig]);
                af[mt][2] = __float_as_uint(As[s][r][kk + tig + 4]);
                af[mt][3] = __float_as_uint(As[s][r + 8][kk + tig + 4]);
            }
            uint32_t bf[8][2];
            int nbase = (warp_n << 6) + gid;
#pragma unroll
            for (int nt = 0; nt < 8; nt++) {
                int c = nbase + (nt << 3);
                bf[nt][0] = __float_as_uint(Bs[s][kk + tig][c]);
                bf[nt][1] = __float_as_uint(Bs[s][kk + tig + 4][c]);
            }
#pragma unroll
            for (int mt = 0; mt < 4; mt++)
#pragma unroll
                for (int nt = 0; nt < 8; nt++)
                    mma_tf32(acc[mt][nt][0], acc[mt][nt][1],
                             acc[mt][nt][2], acc[mt][nt][3],
                             af[mt][0], af[mt][1], af[mt][2], af[mt][3],
                             bf[nt][0], bf[nt][1]);
        }
        cp_wait_all();
        __syncthreads();
    }

#pragma unroll
    for (int mt = 0; mt < 4; mt++) {
#pragma unroll
        for (int nt = 0; nt < 8; nt++) {
            int col = col0 + (warp_n << 6) + (nt << 3) + (tig << 1);
            float bx = bias[col], by = bias[col + 1];
#pragma unroll
            for (int h = 0; h < 2; h++) {
                size_t row = (size_t)row0 + (warp_m << 6) + (mt << 4) + gid + (h << 3);
                float2 o;
                o.x = acc[mt][nt][2 * h + 0] + bx;
                o.y = acc[mt][nt][2 * h + 1] + by;
                if (resid) {
                    float2 rv = *(const float2*)(resid + row * DDIM + col);
                    o.x += rv.x; o.y += rv.y;
                }
                *(float2*)(C + row * DDIM + col) = o;
            }
        }
    }
}

// ---------------------------------------------------------------------------
// Tensor-core windowed attention, 32 q-rows per block, 2 CTAs/SM.
// (R11 version verbatim — part of the measured-best 1749us build.)
// Smem: Ssm[32][516] + KV[2][64][68] = 100864 B.
// ---------------------------------------------------------------------------
#define SS_LD 516
#define QK_LD 68
#define ATTN_SMEM_BYTES ((32 * SS_LD + 2 * 64 * QK_LD) * 4)

__global__ __launch_bounds__(512, 2) void attn_mma_kernel(
    const float* __restrict__ Km, const float* __restrict__ V,
    float* __restrict__ QC)   // Q in, context out (in-place)
{
    extern __shared__ float sm[];
    float* Ssm = sm;                        // [32][516]
    float* KV0 = sm + 32 * SS_LD;           // [64][68] stage 0
    float* KV1 = KV0 + 64 * QK_LD;          // [64][68] stage 1 (Q overlay)

    int tid = threadIdx.x;
    int lane = tid & 31;
    int w = tid >> 5;
    int gid = lane >> 2, tig = lane & 3;
    int nt = w & 7;
    int mg = w >> 3;                        // 0..1
    int mrow = mg << 4;

    int hid = blockIdx.y;                   // (b, win, h)
    int b = hid >> 7;
    int wn = (hid >> 4) & 7;
    int h = hid & 15;
    int t0 = b * 4096 + wn * 512;
    int hcol = h << 6;
    int qbase = blockIdx.x << 5;            // 32 q-rows per block

    int r = tid >> 3;                       // 0..63 KV staging row
    int c0 = (tid & 7) << 3;                // 0..56 staging col (8 floats)

    // ---- stage Q (32x64) into KV1 + prefetch K tile 0 into KV0 ----
    {
        int qr = tid >> 4;                  // 0..31
        int qc = (tid & 15) << 2;           // 0..60
        float4 qv = *(const float4*)(QC + (size_t)(t0 + qbase + qr) * DDIM + hcol + qc);
        const float* ksrc = Km + (size_t)(t0 + r) * DDIM + hcol + c0;
        cp_async16(&KV0[r * QK_LD + c0], ksrc);
        cp_async16(&KV0[r * QK_LD + c0 + 4], ksrc + 4);
        cp_commit();
        *(float4*)&KV1[qr * QK_LD + qc] = qv;
    }
    __syncthreads();                        // Q visible

    // ---- hoist Q A-fragments from KV1 (k-invariant across key tiles) ----
    uint32_t af[8][4];
#pragma unroll
    for (int ks = 0; ks < 8; ks++) {
        int kk = ks << 3;
        af[ks][0] = __float_as_uint(KV1[(mrow + gid) * QK_LD + kk + tig]);
        af[ks][1] = __float_as_uint(KV1[(mrow + gid + 8) * QK_LD + kk + tig]);
        af[ks][2] = __float_as_uint(KV1[(mrow + gid) * QK_LD + kk + tig + 4]);
        af[ks][3] = __float_as_uint(KV1[(mrow + gid + 8) * QK_LD + kk + tig + 4]);
    }
    cp_wait_all();
    __syncthreads();                        // af done (KV1 free), K0 visible

    // ---- scores S[32][512] = Q K^T via mma, pipelined over 8 key tiles ----
    for (int kt = 0; kt < 8; kt++) {
        float* cur = (kt & 1) ? KV1 : KV0;
        if (kt < 7) {
            float* nxt = (kt & 1) ? KV0 : KV1;
            const float* src = Km + (size_t)(t0 + (kt + 1) * 64 + r) * DDIM + hcol + c0;
            cp_async16(&nxt[r * QK_LD + c0], src);
            cp_async16(&nxt[r * QK_LD + c0 + 4], src + 4);
            cp_commit();
        }
        float s0 = 0.f, s1 = 0.f, s2 = 0.f, s3 = 0.f;
#pragma unroll
        for (int ks = 0; ks < 8; ks++) {
            int kk = ks << 3;
            uint32_t b0 = __float_as_uint(cur[((nt << 3) + gid) * QK_LD + kk + tig]);
            uint32_t b1 = __float_as_uint(cur[((nt << 3) + gid) * QK_LD + kk + tig + 4]);
            mma_tf32(s0, s1, s2, s3,
                     af[ks][0], af[ks][1], af[ks][2], af[ks][3], b0, b1);
        }
        {
            int row = mrow + gid;
            int col = kt * 64 + (nt << 3) + (tig << 1);
            *(float2*)&Ssm[row * SS_LD + col] = make_float2(s0, s1);
            *(float2*)&Ssm[(row + 8) * SS_LD + col] = make_float2(s2, s3);
        }
        cp_wait_all();
        __syncthreads();
    }

    // prefetch V tile 0 into KV0 (both buffers free), overlaps softmax
    {
        const float* src = V + (size_t)(t0 + r) * DDIM + hcol + c0;
        cp_async16(&KV0[r * QK_LD + c0], src);
        cp_async16(&KV0[r * QK_LD + c0 + 4], src + 4);
        cp_commit();
    }

    // ---- softmax over 512 keys per row (2 rows per warp), scale 0.125 ----
    {
#pragma unroll
        for (int q = 0; q < 2; q++) {
            int rr = (w << 1) + q;
            float vals[16];
            float m = -1e30f;
#pragma unroll
            for (int t = 0; t < 16; t++) {
                vals[t] = Ssm[rr * SS_LD + lane + 32 * t];
                m = fmaxf(m, vals[t]);
            }
#pragma unroll
            for (int off = 16; off > 0; off >>= 1)
                m = fmaxf(m, __shfl_xor_sync(0xffffffffu, m, off));
            float s = 0.f;
#pragma unroll
            for (int t = 0; t < 16; t++) {
                float e = __expf((vals[t] - m) * 0.125f);
                vals[t] = e;
                s += e;
            }
#pragma unroll
            for (int off = 16; off > 0; off >>= 1)
                s += __shfl_xor_sync(0xffffffffu, s, off);
            float inv = 1.0f / s;
#pragma unroll
            for (int t = 0; t < 16; t++)
                Ssm[rr * SS_LD + lane + 32 * t] = vals[t] * inv;
        }
    }
    cp_wait_all();
    __syncthreads();   // V0 ready; softmax writes visible

    // ---- O[32][64] = P[32][512] @ V[512][64], pipelined ----
    float o0 = 0.f, o1 = 0.f, o2 = 0.f, o3 = 0.f;

    for (int kt = 0; kt < 8; kt++) {
        float* cur = (kt & 1) ? KV1 : KV0;
        if (kt < 7) {
            float* nxt = (kt & 1) ? KV0 : KV1;
            const float* src = V + (size_t)(t0 + (kt + 1) * 64 + r) * DDIM + hcol + c0;
            cp_async16(&nxt[r * QK_LD + c0], src);
            cp_async16(&nxt[r * QK_LD + c0 + 4], src + 4);
            cp_commit();
        }
#pragma unroll
        for (int ks = 0; ks < 8; ks++) {
            int kk = ks << 3;
            uint32_t b0 = __float_as_uint(cur[(kk + tig) * QK_LD + (nt << 3) + gid]);
            uint32_t b1 = __float_as_uint(cur[(kk + tig + 4) * QK_LD + (nt << 3) + gid]);
            int kc = kt * 64 + kk;
            uint32_t a0 = __float_as_uint(Ssm[(mrow + gid) * SS_LD + kc + tig]);
            uint32_t a1 = __float_as_uint(Ssm[(mrow + gid + 8) * SS_LD + kc + tig]);
            uint32_t a2 = __float_as_uint(Ssm[(mrow + gid) * SS_LD + kc + tig + 4]);
            uint32_t a3 = __float_as_uint(Ssm[(mrow + gid + 8) * SS_LD + kc + tig + 4]);
            mma_tf32(o0, o1, o2, o3, a0, a1, a2, a3, b0, b1);
        }
        cp_wait_all();
        __syncthreads();
    }

    // ---- store context in-place over Q ----
    {
        size_t row = (size_t)t0 + qbase + mrow + gid;
        int col = hcol + (nt << 3) + (tig << 1);
        *(float2*)(QC + row * DDIM + col) = make_float2(o0, o1);
        *(float2*)(QC + (row + 8) * DDIM + col) = make_float2(o2, o3);
    }
}

// ---------------------------------------------------------------------------
// LayerNorm per row (1024 elems), keras eps = 1e-3. One block per row.
// ---------------------------------------------------------------------------
__global__ __launch_bounds__(256) void ln_kernel(
    const float* __restrict__ Y, const float* __restrict__ gamma,
    const float* __restrict__ beta, float* __restrict__ out)
{
    int row = blockIdx.x;
    int tid = threadIdx.x;
    const float* y = Y + (size_t)row * DDIM;

    float4 v = *(const float4*)(y + tid * 4);
    float s  = v.x + v.y + v.z + v.w;
    float sq = v.x * v.x + v.y * v.y + v.z * v.z + v.w * v.w;

#pragma unroll
    for (int off = 16; off > 0; off >>= 1) {
        s  += __shfl_xor_sync(0xffffffffu, s, off);
        sq += __shfl_xor_sync(0xffffffffu, sq, off);
    }
    __shared__ float ss[8], ssq[8];
    int lane = tid & 31, wid = tid >> 5;
    if (lane == 0) { ss[wid] = s; ssq[wid] = sq; }
    __syncthreads();
    float S = 0.f, SQ = 0.f;
#pragma unroll
    for (int i = 0; i < 8; i++) { S += ss[i]; SQ += ssq[i]; }

    float mu  = S * (1.0f / 1024.0f);
    float var = SQ * (1.0f / 1024.0f) - mu * mu;
    float inv = rsqrtf(var + 1e-3f);

    float4 g  = *(const float4*)(gamma + tid * 4);
    float4 be = *(const float4*)(beta + tid * 4);
    float4 o;
    o.x = (v.x - mu) * inv * g.x + be.x;
    o.y = (v.y - mu) * inv * g.y + be.y;
    o.z = (v.z - mu) * inv * g.z + be.z;
    o.w = (v.w - mu) * inv * g.w + be.w;
    *(float4*)(out + (size_t)row * DDIM + tid * 4) = o;
}

// ---------------------------------------------------------------------------
extern "C" void kernel_launch(void* const* d_in, const int* in_sizes, int n_in,
                              void* d_out, int out_size)
{
    const float* x     = (const float*)d_in[0];
    const float* Wq    = (const float*)d_in[1];
    const float* bq    = (const float*)d_in[2];
    const float* Wk    = (const float*)d_in[3];
    const float* bk    = (const float*)d_in[4];
    const float* Wv    = (const float*)d_in[5];
    const float* bv    = (const float*)d_in[6];
    const float* Wo    = (const float*)d_in[7];
    const float* bo    = (const float*)d_in[8];
    const float* gamma = (const float*)d_in[9];
    const float* beta  = (const float*)d_in[10];
    float* out = (float*)d_out;
    (void)in_sizes; (void)n_in; (void)out_size;

    float *Qp, *Kp, *Vp;
    cudaGetSymbolAddress((void**)&Qp, g_Q);
    cudaGetSymbolAddress((void**)&Kp, g_K);
    cudaGetSymbolAddress((void**)&Vp, g_V);

    cudaFuncSetAttribute(tf32_gemm3_kernel,
                         cudaFuncAttributeMaxDynamicSharedMemorySize, GEMM_SMEM_BYTES);
    cudaFuncSetAttribute(attn_mma_kernel,
                         cudaFuncAttributeMaxDynamicSharedMemorySize, ATTN_SMEM_BYTES);

    // Q, K, V in one launch: z selects weights/bias/output
    tf32_gemm3_kernel<<<dim3(8, 64, 3), 256, GEMM_SMEM_BYTES>>>(
        x, Wq, Wk, Wv, bq, bk, bv, nullptr, Qp, Kp, Vp);

    // ctx overwrites Q in-place; grid: 16 q-tiles of 32 x 512 heads
    attn_mma_kernel<<<dim3(16, 512), 512, ATTN_SMEM_BYTES>>>(Kp, Vp, Qp);

    // Y = ctx @ Wo + bo + x   (write Y into g_K, dead after attention)
    tf32_gemm3_kernel<<<dim3(8, 64, 1), 256, GEMM_SMEM_BYTES>>>(
        Qp, Wo, Wo, Wo, bo, bo, bo, x, Kp, Kp, Kp);

    ln_kernel<<<M_TOK, 256>>>(Kp, gamma, beta, out);
}

// round 15
// speedup vs baseline: 2.0600x; 1.4674x over previous
#include <cuda_runtime.h>
#include <cuda_fp16.h>
#include <math.h>
#include <stdint.h>

// Problem constants (fixed by the dataset instance)
#define M_TOK 16384   // B*S = 4*4096
#define DDIM  1024    // model dim = H*Khead = 16*64
// windows: 8 of 512 tokens; heads: 16 of dim 64

// Static device scratch (allocation-free rule)
__device__ float  g_Q[(size_t)M_TOK * DDIM];
__device__ float  g_K[(size_t)M_TOK * DDIM];
__device__ float  g_V[(size_t)M_TOK * DDIM];
__device__ __half g_xh[(size_t)M_TOK * DDIM];          // x (then ctx) as half
__device__ __half g_Wh[(size_t)4 * DDIM * DDIM];       // 4 weights, half, [n][k]

// fp16 mma m16n8k16, fp32 accumulate: 2048 MACs/instr (2x tf32 m16n8k8).
__device__ __forceinline__ void mma_f16(
    float& d0, float& d1, float& d2, float& d3,
    uint32_t a0, uint32_t a1, uint32_t a2, uint32_t a3,
    uint32_t b0, uint32_t b1)
{
    asm volatile(
        "mma.sync.aligned.m16n8k16.row.col.f32.f16.f16.f32 "
        "{%0,%1,%2,%3}, {%4,%5,%6,%7}, {%8,%9}, {%0,%1,%2,%3};"
        : "+f"(d0), "+f"(d1), "+f"(d2), "+f"(d3)
        : "r"(a0), "r"(a1), "r"(a2), "r"(a3), "r"(b0), "r"(b1));
}

// tf32 mma (attention, unchanged): raw fp32 == tf32 truncation.
__device__ __forceinline__ void mma_tf32(
    float& d0, float& d1, float& d2, float& d3,
    uint32_t a0, uint32_t a1, uint32_t a2, uint32_t a3,
    uint32_t b0, uint32_t b1)
{
    asm volatile(
        "mma.sync.aligned.m16n8k8.row.col.f32.tf32.tf32.f32 "
        "{%0,%1,%2,%3}, {%4,%5,%6,%7}, {%8,%9}, {%0,%1,%2,%3};"
        : "+f"(d0), "+f"(d1), "+f"(d2), "+f"(d3)
        : "r"(a0), "r"(a1), "r"(a2), "r"(a3), "r"(b0), "r"(b1));
}

__device__ __forceinline__ void cp_async16(void* smem_dst, const void* gsrc) {
    uint32_t s = (uint32_t)__cvta_generic_to_shared(smem_dst);
    asm volatile("cp.async.cg.shared.global [%0], [%1], 16;" :: "r"(s), "l"(gsrc));
}
__device__ __forceinline__ void cp_commit() {
    asm volatile("cp.async.commit_group;");
}
__device__ __forceinline__ void cp_wait_all() {
    asm volatile("cp.async.wait_group 0;");
}

// ---------------------------------------------------------------------------
// Prep: transpose+convert weights fp32 [k][n] -> half [n][k].  grid(32,32,4).
// ---------------------------------------------------------------------------
__global__ __launch_bounds__(256) void wcvt_kernel(
    const float* __restrict__ Wq, const float* __restrict__ Wk,
    const float* __restrict__ Wv, const float* __restrict__ Wo,
    __half* __restrict__ out)
{
    int z = blockIdx.z;
    const float* W = (z == 0) ? Wq : (z == 1) ? Wk : (z == 2) ? Wv : Wo;
    __shared__ float t[32][33];
    int r0 = blockIdx.y << 5, c0 = blockIdx.x << 5;
    int tc = threadIdx.x & 31, tr = threadIdx.x >> 5;   // tr 0..7
#pragma unroll
    for (int i = 0; i < 4; i++) {
        int rr = tr + i * 8;
        t[rr][tc] = W[(size_t)(r0 + rr) * DDIM + c0 + tc];
    }
    __syncthreads();
    __half* o = out + (size_t)z * DDIM * DDIM;
#pragma unroll
    for (int i = 0; i < 4; i++) {
        int rr = tr + i * 8;
        o[(size_t)(c0 + rr) * DDIM + r0 + tc] = __float2half(t[tc][rr]);
    }
}

// ---------------------------------------------------------------------------
// Prep: fp32 -> half elementwise (x, then ctx). grid 16384 x 256, 4 per thr.
// ---------------------------------------------------------------------------
__global__ __launch_bounds__(256) void f2h_kernel(
    const float* __restrict__ in, __half* __restrict__ out)
{
    size_t i = ((size_t)blockIdx.x * 256 + threadIdx.x) * 4;
    float4 v = *(const float4*)(in + i);
    __half2 h0 = __floats2half2_rn(v.x, v.y);
    __half2 h1 = __floats2half2_rn(v.z, v.w);
    *(__half2*)(out + i) = h0;
    *(__half2*)(out + i + 2) = h1;
}

// ---------------------------------------------------------------------------
// FP16 tensor-core GEMM, 3-output variant (z selects Bt/bias/C).
// C[M,1024] = A_half[M,1024] @ Bt_half[n][k]^T + bias (+ resid), fp32 out.
// 128x128x32 block tile, 256 threads = 8 warps (4 m x 2 n), warp 32x64.
// 2-stage cp.async (R8 structure). Smem half tiles, stride 40 halves
// (word idx gid*20+tig spans all 32 banks -> conflict-free frags).
// dyn smem: 2*(128*40 + 128*40)*2 = 40960 B
// ---------------------------------------------------------------------------
#define GEMM_SMEM_BYTES (2 * (128 * 40 + 128 * 40) * 2)

__global__ __launch_bounds__(256) void h_gemm3_kernel(
    const __half* __restrict__ A,
    const __half* __restrict__ Bt0, const __half* __restrict__ Bt1,
    const __half* __restrict__ Bt2,
    const float* __restrict__ bias0, const float* __restrict__ bias1,
    const float* __restrict__ bias2,
    const float* __restrict__ resid,
    float* __restrict__ C0, float* __restrict__ C1, float* __restrict__ C2)
{
    extern __shared__ __half hsm[];
    __half (*As)[128][40] = (__half(*)[128][40])hsm;               // [2][128][40]
    __half (*Bs)[128][40] = (__half(*)[128][40])(hsm + 2 * 128 * 40);

    int z = blockIdx.z;
    const __half* Bt  = (z == 0) ? Bt0 : (z == 1) ? Bt1 : Bt2;
    const float* bias = (z == 0) ? bias0 : (z == 1) ? bias1 : bias2;
    float* C          = (z == 0) ? C0 : (z == 1) ? C1 : C2;

    int tid = threadIdx.x;
    int lane = tid & 31, wid = tid >> 5;
    int warp_m = wid & 3;              // 4 warps over M (32 rows each)
    int warp_n = wid >> 2;             // 2 warps over N (64 cols each)
    int gid = lane >> 2, tig = lane & 3;

    int row0 = blockIdx.y << 7;
    int col0 = blockIdx.x << 7;

    float acc[2][8][4];
#pragma unroll
    for (int mt = 0; mt < 2; mt++)
#pragma unroll
        for (int nt = 0; nt < 8; nt++)
#pragma unroll
            for (int r = 0; r < 4; r++) acc[mt][nt][r] = 0.f;

    // staging: tile rows 128, 32 halves (64B) per row = 2 x 16-half chunks
    int rowS = tid >> 1;               // 0..127
    int colS = (tid & 1) << 4;         // 0 or 16 halves

    const __half* Ag = A + (size_t)(row0 + rowS) * DDIM + colS;
    const __half* Bg = Bt + (size_t)(col0 + rowS) * DDIM + colS;

    // preamble: stage tile 0 (k halves 0..31)
    cp_async16(&As[0][rowS][colS], Ag);
    cp_async16(&As[0][rowS][colS + 8], Ag + 8);
    cp_async16(&Bs[0][rowS][colS], Bg);
    cp_async16(&Bs[0][rowS][colS + 8], Bg + 8);
    cp_commit();
    cp_wait_all();
    __syncthreads();

    for (int t = 0; t < 32; t++) {
        if (t < 31) {
            int sn = (t + 1) & 1;
            int k0n = (t + 1) << 5;    // halves
            cp_async16(&As[sn][rowS][colS], Ag + k0n);
            cp_async16(&As[sn][rowS][colS + 8], Ag + k0n + 8);
            cp_async16(&Bs[sn][rowS][colS], Bg + k0n);
            cp_async16(&Bs[sn][rowS][colS + 8], Bg + k0n + 8);
            cp_commit();
        }

        int s = t & 1;
#pragma unroll
        for (int ks = 0; ks < 2; ks++) {
            int kk = ks << 4;          // k halves 0 or 16
            uint32_t af[2][4];
            int mrow = (warp_m << 5) + gid;
#pragma unroll
            for (int mt = 0; mt < 2; mt++) {
                int r = mrow + (mt << 4);
                af[mt][0] = *(const uint32_t*)&As[s][r][kk + (tig << 1)];
                af[mt][1] = *(const uint32_t*)&As[s][r + 8][kk + (tig << 1)];
                af[mt][2] = *(const uint32_t*)&As[s][r][kk + (tig << 1) + 8];
                af[mt][3] = *(const uint32_t*)&As[s][r + 8][kk + (tig << 1) + 8];
            }
            uint32_t bf[8][2];
            int nbase = (warp_n << 6) + gid;
#pragma unroll
            for (int nt = 0; nt < 8; nt++) {
                int c = nbase + (nt << 3);
                bf[nt][0] = *(const uint32_t*)&Bs[s][c][kk + (tig << 1)];
                bf[nt][1] = *(const uint32_t*)&Bs[s][c][kk + (tig << 1) + 8];
            }
#pragma unroll
            for (int mt = 0; mt < 2; mt++)
#pragma unroll
                for (int nt = 0; nt < 8; nt++)
                    mma_f16(acc[mt][nt][0], acc[mt][nt][1],
                            acc[mt][nt][2], acc[mt][nt][3],
                            af[mt][0], af[mt][1], af[mt][2], af[mt][3],
                            bf[nt][0], bf[nt][1]);
        }
        cp_wait_all();
        __syncthreads();
    }

#pragma unroll
    for (int mt = 0; mt < 2; mt++) {
#pragma unroll
        for (int nt = 0; nt < 8; nt++) {
            int col = col0 + (warp_n << 6) + (nt << 3) + (tig << 1);
            float bx = bias[col], by = bias[col + 1];
#pragma unroll
            for (int h = 0; h < 2; h++) {
                size_t row = (size_t)row0 + (warp_m << 5) + (mt << 4) + gid + (h << 3);
                float2 o;
                o.x = acc[mt][nt][2 * h + 0] + bx;
                o.y = acc[mt][nt][2 * h + 1] + by;
                if (resid) {
                    float2 rv = *(const float2*)(resid + row * DDIM + col);
                    o.x += rv.x; o.y += rv.y;
                }
                *(float2*)(C + row * DDIM + col) = o;
            }
        }
    }
}

// ---------------------------------------------------------------------------
// Tensor-core windowed attention, 32 q-rows per block, 2 CTAs/SM.
// (R11 version verbatim — part of the measured-best 1749us build.)
// Smem: Ssm[32][516] + KV[2][64][68] = 100864 B.
// ---------------------------------------------------------------------------
#define SS_LD 516
#define QK_LD 68
#define ATTN_SMEM_BYTES ((32 * SS_LD + 2 * 64 * QK_LD) * 4)

__global__ __launch_bounds__(512, 2) void attn_mma_kernel(
    const float* __restrict__ Km, const float* __restrict__ V,
    float* __restrict__ QC)   // Q in, context out (in-place)
{
    extern __shared__ float sm[];
    float* Ssm = sm;                        // [32][516]
    float* KV0 = sm + 32 * SS_LD;           // [64][68] stage 0
    float* KV1 = KV0 + 64 * QK_LD;          // [64][68] stage 1 (Q overlay)

    int tid = threadIdx.x;
    int lane = tid & 31;
    int w = tid >> 5;
    int gid = lane >> 2, tig = lane & 3;
    int nt = w & 7;
    int mg = w >> 3;                        // 0..1
    int mrow = mg << 4;

    int hid = blockIdx.y;                   // (b, win, h)
    int b = hid >> 7;
    int wn = (hid >> 4) & 7;
    int h = hid & 15;
    int t0 = b * 4096 + wn * 512;
    int hcol = h << 6;
    int qbase = blockIdx.x << 5;            // 32 q-rows per block

    int r = tid >> 3;                       // 0..63 KV staging row
    int c0 = (tid & 7) << 3;                // 0..56 staging col (8 floats)

    // ---- stage Q (32x64) into KV1 + prefetch K tile 0 into KV0 ----
    {
        int qr = tid >> 4;                  // 0..31
        int qc = (tid & 15) << 2;           // 0..60
        float4 qv = *(const float4*)(QC + (size_t)(t0 + qbase + qr) * DDIM + hcol + qc);
        const float* ksrc = Km + (size_t)(t0 + r) * DDIM + hcol + c0;
        cp_async16(&KV0[r * QK_LD + c0], ksrc);
        cp_async16(&KV0[r * QK_LD + c0 + 4], ksrc + 4);
        cp_commit();
        *(float4*)&KV1[qr * QK_LD + qc] = qv;
    }
    __syncthreads();                        // Q visible

    // ---- hoist Q A-fragments from KV1 (k-invariant across key tiles) ----
    uint32_t af[8][4];
#pragma unroll
    for (int ks = 0; ks < 8; ks++) {
        int kk = ks << 3;
        af[ks][0] = __float_as_uint(KV1[(mrow + gid) * QK_LD + kk + tig]);
        af[ks][1] = __float_as_uint(KV1[(mrow + gid + 8) * QK_LD + kk + tig]);
        af[ks][2] = __float_as_uint(KV1[(mrow + gid) * QK_LD + kk + tig + 4]);
        af[ks][3] = __float_as_uint(KV1[(mrow + gid + 8) * QK_LD + kk + tig + 4]);
    }
    cp_wait_all();
    __syncthreads();                        // af done (KV1 free), K0 visible

    // ---- scores S[32][512] = Q K^T via mma, pipelined over 8 key tiles ----
    for (int kt = 0; kt < 8; kt++) {
        float* cur = (kt & 1) ? KV1 : KV0;
        if (kt < 7) {
            float* nxt = (kt & 1) ? KV0 : KV1;
            const float* src = Km + (size_t)(t0 + (kt + 1) * 64 + r) * DDIM + hcol + c0;
            cp_async16(&nxt[r * QK_LD + c0], src);
            cp_async16(&nxt[r * QK_LD + c0 + 4], src + 4);
            cp_commit();
        }
        float s0 = 0.f, s1 = 0.f, s2 = 0.f, s3 = 0.f;
#pragma unroll
        for (int ks = 0; ks < 8; ks++) {
            int kk = ks << 3;
            uint32_t b0 = __float_as_uint(cur[((nt << 3) + gid) * QK_LD + kk + tig]);
            uint32_t b1 = __float_as_uint(cur[((nt << 3) + gid) * QK_LD + kk + tig + 4]);
            mma_tf32(s0, s1, s2, s3,
                     af[ks][0], af[ks][1], af[ks][2], af[ks][3], b0, b1);
        }
        {
            int row = mrow + gid;
            int col = kt * 64 + (nt << 3) + (tig << 1);
            *(float2*)&Ssm[row * SS_LD + col] = make_float2(s0, s1);
            *(float2*)&Ssm[(row + 8) * SS_LD + col] = make_float2(s2, s3);
        }
        cp_wait_all();
        __syncthreads();
    }

    // prefetch V tile 0 into KV0 (both buffers free), overlaps softmax
    {
        const float* src = V + (size_t)(t0 + r) * DDIM + hcol + c0;
        cp_async16(&KV0[r * QK_LD + c0], src);
        cp_async16(&KV0[r * QK_LD + c0 + 4], src + 4);
        cp_commit();
    }

    // ---- softmax over 512 keys per row (2 rows per warp), scale 0.125 ----
    {
#pragma unroll
        for (int q = 0; q < 2; q++) {
            int rr = (w << 1) + q;
            float vals[16];
            float m = -1e30f;
#pragma unroll
            for (int t = 0; t < 16; t++) {
                vals[t] = Ssm[rr * SS_LD + lane + 32 * t];
                m = fmaxf(m, vals[t]);
            }
#pragma unroll
            for (int off = 16; off > 0; off >>= 1)
                m = fmaxf(m, __shfl_xor_sync(0xffffffffu, m, off));
            float s = 0.f;
#pragma unroll
            for (int t = 0; t < 16; t++) {
                float e = __expf((vals[t] - m) * 0.125f);
                vals[t] = e;
                s += e;
            }
#pragma unroll
            for (int off = 16; off > 0; off >>= 1)
                s += __shfl_xor_sync(0xffffffffu, s, off);
            float inv = 1.0f / s;
#pragma unroll
            for (int t = 0; t < 16; t++)
                Ssm[rr * SS_LD + lane + 32 * t] = vals[t] * inv;
        }
    }
    cp_wait_all();
    __syncthreads();   // V0 ready; softmax writes visible

    // ---- O[32][64] = P[32][512] @ V[512][64], pipelined ----
    float o0 = 0.f, o1 = 0.f, o2 = 0.f, o3 = 0.f;

    for (int kt = 0; kt < 8; kt++) {
        float* cur = (kt & 1) ? KV1 : KV0;
        if (kt < 7) {
            float* nxt = (kt & 1) ? KV0 : KV1;
            const float* src = V + (size_t)(t0 + (kt + 1) * 64 + r) * DDIM + hcol + c0;
            cp_async16(&nxt[r * QK_LD + c0], src);
            cp_async16(&nxt[r * QK_LD + c0 + 4], src + 4);
            cp_commit();
        }
#pragma unroll
        for (int ks = 0; ks < 8; ks++) {
            int kk = ks << 3;
            uint32_t b0 = __float_as_uint(cur[(kk + tig) * QK_LD + (nt << 3) + gid]);
            uint32_t b1 = __float_as_uint(cur[(kk + tig + 4) * QK_LD + (nt << 3) + gid]);
            int kc = kt * 64 + kk;
            uint32_t a0 = __float_as_uint(Ssm[(mrow + gid) * SS_LD + kc + tig]);
            uint32_t a1 = __float_as_uint(Ssm[(mrow + gid + 8) * SS_LD + kc + tig]);
            uint32_t a2 = __float_as_uint(Ssm[(mrow + gid) * SS_LD + kc + tig + 4]);
            uint32_t a3 = __float_as_uint(Ssm[(mrow + gid + 8) * SS_LD + kc + tig + 4]);
            mma_tf32(o0, o1, o2, o3, a0, a1, a2, a3, b0, b1);
        }
        cp_wait_all();
        __syncthreads();
    }

    // ---- store context in-place over Q ----
    {
        size_t row = (size_t)t0 + qbase + mrow + gid;
        int col = hcol + (nt << 3) + (tig << 1);
        *(float2*)(QC + row * DDIM + col) = make_float2(o0, o1);
        *(float2*)(QC + (row + 8) * DDIM + col) = make_float2(o2, o3);
    }
}

// ---------------------------------------------------------------------------
// LayerNorm per row (1024 elems), keras eps = 1e-3. One block per row.
// ---------------------------------------------------------------------------
__global__ __launch_bounds__(256) void ln_kernel(
    const float* __restrict__ Y, const float* __restrict__ gamma,
    const float* __restrict__ beta, float* __restrict__ out)
{
    int row = blockIdx.x;
    int tid = threadIdx.x;
    const float* y = Y + (size_t)row * DDIM;

    float4 v = *(const float4*)(y + tid * 4);
    float s  = v.x + v.y + v.z + v.w;
    float sq = v.x * v.x + v.y * v.y + v.z * v.z + v.w * v.w;

#pragma unroll
    for (int off = 16; off > 0; off >>= 1) {
        s  += __shfl_xor_sync(0xffffffffu, s, off);
        sq += __shfl_xor_sync(0xffffffffu, sq, off);
    }
    __shared__ float ss[8], ssq[8];
    int lane = tid & 31, wid = tid >> 5;
    if (lane == 0) { ss[wid] = s; ssq[wid] = sq; }
    __syncthreads();
    float S = 0.f, SQ = 0.f;
#pragma unroll
    for (int i = 0; i < 8; i++) { S += ss[i]; SQ += ssq[i]; }

    float mu  = S * (1.0f / 1024.0f);
    float var = SQ * (1.0f / 1024.0f) - mu * mu;
    float inv = rsqrtf(var + 1e-3f);

    float4 g  = *(const float4*)(gamma + tid * 4);
    float4 be = *(const float4*)(beta + tid * 4);
    float4 o;
    o.x = (v.x - mu) * inv * g.x + be.x;
    o.y = (v.y - mu) * inv * g.y + be.y;
    o.z = (v.z - mu) * inv * g.z + be.z;
    o.w = (v.w - mu) * inv * g.w + be.w;
    *(float4*)(out + (size_t)row * DDIM + tid * 4) = o;
}

// ---------------------------------------------------------------------------
extern "C" void kernel_launch(void* const* d_in, const int* in_sizes, int n_in,
                              void* d_out, int out_size)
{
    const float* x     = (const float*)d_in[0];
    const float* Wq    = (const float*)d_in[1];
    const float* bq    = (const float*)d_in[2];
    const float* Wk    = (const float*)d_in[3];
    const float* bk    = (const float*)d_in[4];
    const float* Wv    = (const float*)d_in[5];
    const float* bv    = (const float*)d_in[6];
    const float* Wo    = (const float*)d_in[7];
    const float* bo    = (const float*)d_in[8];
    const float* gamma = (const float*)d_in[9];
    const float* beta  = (const float*)d_in[10];
    float* out = (float*)d_out;
    (void)in_sizes; (void)n_in; (void)out_size;

    float *Qp, *Kp, *Vp;
    __half *xhp, *Whp;
    cudaGetSymbolAddress((void**)&Qp, g_Q);
    cudaGetSymbolAddress((void**)&Kp, g_K);
    cudaGetSymbolAddress((void**)&Vp, g_V);
    cudaGetSymbolAddress((void**)&xhp, g_xh);
    cudaGetSymbolAddress((void**)&Whp, g_Wh);

    cudaFuncSetAttribute(h_gemm3_kernel,
                         cudaFuncAttributeMaxDynamicSharedMemorySize, GEMM_SMEM_BYTES);
    cudaFuncSetAttribute(attn_mma_kernel,
                         cudaFuncAttributeMaxDynamicSharedMemorySize, ATTN_SMEM_BYTES);

    const size_t WSZ = (size_t)DDIM * DDIM;

    // prep: weights -> half [n][k]; x -> half
    wcvt_kernel<<<dim3(32, 32, 4), 256>>>(Wq, Wk, Wv, Wo, Whp);
    f2h_kernel<<<16384, 256>>>(x, xhp);

    // Q, K, V in one launch (fp16 mma): z selects weights/bias/output
    h_gemm3_kernel<<<dim3(8, 128, 3), 256, GEMM_SMEM_BYTES>>>(
        xhp, Whp, Whp + WSZ, Whp + 2 * WSZ, bq, bk, bv, nullptr, Qp, Kp, Vp);

    // ctx overwrites Q in-place (fp32 path, unchanged)
    attn_mma_kernel<<<dim3(16, 512), 512, ATTN_SMEM_BYTES>>>(Kp, Vp, Qp);

    // ctx -> half (reuse x-half buffer)
    f2h_kernel<<<16384, 256>>>(Qp, xhp);

    // Y = ctx @ Wo + bo + x   (write Y into g_K)
    h_gemm3_kernel<<<dim3(8, 128, 1), 256, GEMM_SMEM_BYTES>>>(
        xhp, Whp + 3 * WSZ, Whp + 3 * WSZ, Whp + 3 * WSZ,
        bo, bo, bo, x, Kp, Kp, Kp);

    ln_kernel<<<M_TOK, 256>>>(Kp, gamma, beta, out);
}

// round 16
// speedup vs baseline: 2.6219x; 1.2728x over previous
#include <cuda_runtime.h>
#include <cuda_fp16.h>
#include <math.h>
#include <stdint.h>

// Problem constants (fixed by the dataset instance)
#define M_TOK 16384   // B*S = 4*4096
#define DDIM  1024    // model dim = H*Khead = 16*64
// windows: 8 of 512 tokens; heads: 16 of dim 64

// Static device scratch (allocation-free rule)
__device__ __half g_Qh[(size_t)M_TOK * DDIM];          // Q half
__device__ __half g_Kh[(size_t)M_TOK * DDIM];          // K half
__device__ __half g_Vh[(size_t)M_TOK * DDIM];          // V half
__device__ __half g_xh[(size_t)M_TOK * DDIM];          // x-half, then ctx-half
__device__ float  g_Y [(size_t)M_TOK * DDIM];          // Y = ctx@Wo+bo+x
__device__ __half g_Wh[(size_t)4 * DDIM * DDIM];       // 4 weights, half, [n][k]

// fp16 mma m16n8k16, fp32 accumulate.
__device__ __forceinline__ void mma_f16(
    float& d0, float& d1, float& d2, float& d3,
    uint32_t a0, uint32_t a1, uint32_t a2, uint32_t a3,
    uint32_t b0, uint32_t b1)
{
    asm volatile(
        "mma.sync.aligned.m16n8k16.row.col.f32.f16.f16.f32 "
        "{%0,%1,%2,%3}, {%4,%5,%6,%7}, {%8,%9}, {%0,%1,%2,%3};"
        : "+f"(d0), "+f"(d1), "+f"(d2), "+f"(d3)
        : "r"(a0), "r"(a1), "r"(a2), "r"(a3), "r"(b0), "r"(b1));
}

__device__ __forceinline__ void cp_async16(void* smem_dst, const void* gsrc) {
    uint32_t s = (uint32_t)__cvta_generic_to_shared(smem_dst);
    asm volatile("cp.async.cg.shared.global [%0], [%1], 16;" :: "r"(s), "l"(gsrc));
}
__device__ __forceinline__ void cp_commit() {
    asm volatile("cp.async.commit_group;");
}
__device__ __forceinline__ void cp_wait_all() {
    asm volatile("cp.async.wait_group 0;");
}

__device__ __forceinline__ uint32_t pack_h2(__half lo, __half hi) {
    __half2 h = __halves2half2(lo, hi);
    return *(uint32_t*)&h;
}

// ---------------------------------------------------------------------------
// Prep: transpose+convert weights fp32 [k][n] -> half [n][k].  grid(32,32,4).
// ---------------------------------------------------------------------------
__global__ __launch_bounds__(256) void wcvt_kernel(
    const float* __restrict__ Wq, const float* __restrict__ Wk,
    const float* __restrict__ Wv, const float* __restrict__ Wo,
    __half* __restrict__ out)
{
    int z = blockIdx.z;
    const float* W = (z == 0) ? Wq : (z == 1) ? Wk : (z == 2) ? Wv : Wo;
    __shared__ float t[32][33];
    int r0 = blockIdx.y << 5, c0 = blockIdx.x << 5;
    int tc = threadIdx.x & 31, tr = threadIdx.x >> 5;   // tr 0..7
#pragma unroll
    for (int i = 0; i < 4; i++) {
        int rr = tr + i * 8;
        t[rr][tc] = W[(size_t)(r0 + rr) * DDIM + c0 + tc];
    }
    __syncthreads();
    __half* o = out + (size_t)z * DDIM * DDIM;
#pragma unroll
    for (int i = 0; i < 4; i++) {
        int rr = tr + i * 8;
        o[(size_t)(c0 + rr) * DDIM + r0 + tc] = __float2half(t[tc][rr]);
    }
}

// ---------------------------------------------------------------------------
// Prep: fp32 -> half elementwise (x). grid 16384 x 256, 4 per thread.
// ---------------------------------------------------------------------------
__global__ __launch_bounds__(256) void f2h_kernel(
    const float* __restrict__ in, __half* __restrict__ out)
{
    size_t i = ((size_t)blockIdx.x * 256 + threadIdx.x) * 4;
    float4 v = *(const float4*)(in + i);
    *(__half2*)(out + i) = __floats2half2_rn(v.x, v.y);
    *(__half2*)(out + i + 2) = __floats2half2_rn(v.z, v.w);
}

// ---------------------------------------------------------------------------
// FP16 GEMM core macro-structure shared by the two variants below:
// 128x128x32 tile, 256 thr = 8 warps (4m x 2n), 2-stage cp.async.
// dyn smem: 2*(128*40 + 128*40)*2 = 40960 B
// ---------------------------------------------------------------------------
#define GEMM_SMEM_BYTES (2 * (128 * 40 + 128 * 40) * 2)

// Variant 1: QKV — half outputs, no resid. z selects (Bt, bias, C).
__global__ __launch_bounds__(256) void h_gemm3h_kernel(
    const __half* __restrict__ A,
    const __half* __restrict__ Bt0, const __half* __restrict__ Bt1,
    const __half* __restrict__ Bt2,
    const float* __restrict__ bias0, const float* __restrict__ bias1,
    const float* __restrict__ bias2,
    __half* __restrict__ C0, __half* __restrict__ C1, __half* __restrict__ C2)
{
    extern __shared__ __half hsm[];
    __half (*As)[128][40] = (__half(*)[128][40])hsm;
    __half (*Bs)[128][40] = (__half(*)[128][40])(hsm + 2 * 128 * 40);

    int z = blockIdx.z;
    const __half* Bt  = (z == 0) ? Bt0 : (z == 1) ? Bt1 : Bt2;
    const float* bias = (z == 0) ? bias0 : (z == 1) ? bias1 : bias2;
    __half* C         = (z == 0) ? C0 : (z == 1) ? C1 : C2;

    int tid = threadIdx.x;
    int lane = tid & 31, wid = tid >> 5;
    int warp_m = wid & 3, warp_n = wid >> 2;
    int gid = lane >> 2, tig = lane & 3;
    int row0 = blockIdx.y << 7, col0 = blockIdx.x << 7;

    float acc[2][8][4];
#pragma unroll
    for (int mt = 0; mt < 2; mt++)
#pragma unroll
        for (int nt = 0; nt < 8; nt++)
#pragma unroll
            for (int r = 0; r < 4; r++) acc[mt][nt][r] = 0.f;

    int rowS = tid >> 1, colS = (tid & 1) << 4;
    const __half* Ag = A + (size_t)(row0 + rowS) * DDIM + colS;
    const __half* Bg = Bt + (size_t)(col0 + rowS) * DDIM + colS;

    cp_async16(&As[0][rowS][colS], Ag);
    cp_async16(&As[0][rowS][colS + 8], Ag + 8);
    cp_async16(&Bs[0][rowS][colS], Bg);
    cp_async16(&Bs[0][rowS][colS + 8], Bg + 8);
    cp_commit(); cp_wait_all(); __syncthreads();

    for (int t = 0; t < 32; t++) {
        if (t < 31) {
            int sn = (t + 1) & 1, k0n = (t + 1) << 5;
            cp_async16(&As[sn][rowS][colS], Ag + k0n);
            cp_async16(&As[sn][rowS][colS + 8], Ag + k0n + 8);
            cp_async16(&Bs[sn][rowS][colS], Bg + k0n);
            cp_async16(&Bs[sn][rowS][colS + 8], Bg + k0n + 8);
            cp_commit();
        }
        int s = t & 1;
#pragma unroll
        for (int ks = 0; ks < 2; ks++) {
            int kk = ks << 4;
            uint32_t af[2][4];
            int mrow = (warp_m << 5) + gid;
#pragma unroll
            for (int mt = 0; mt < 2; mt++) {
                int r = mrow + (mt << 4);
                af[mt][0] = *(const uint32_t*)&As[s][r][kk + (tig << 1)];
                af[mt][1] = *(const uint32_t*)&As[s][r + 8][kk + (tig << 1)];
                af[mt][2] = *(const uint32_t*)&As[s][r][kk + (tig << 1) + 8];
                af[mt][3] = *(const uint32_t*)&As[s][r + 8][kk + (tig << 1) + 8];
            }
            uint32_t bf[8][2];
            int nbase = (warp_n << 6) + gid;
#pragma unroll
            for (int nt = 0; nt < 8; nt++) {
                int c = nbase + (nt << 3);
                bf[nt][0] = *(const uint32_t*)&Bs[s][c][kk + (tig << 1)];
                bf[nt][1] = *(const uint32_t*)&Bs[s][c][kk + (tig << 1) + 8];
            }
#pragma unroll
            for (int mt = 0; mt < 2; mt++)
#pragma unroll
                for (int nt = 0; nt < 8; nt++)
                    mma_f16(acc[mt][nt][0], acc[mt][nt][1],
                            acc[mt][nt][2], acc[mt][nt][3],
                            af[mt][0], af[mt][1], af[mt][2], af[mt][3],
                            bf[nt][0], bf[nt][1]);
        }
        cp_wait_all(); __syncthreads();
    }

#pragma unroll
    for (int mt = 0; mt < 2; mt++) {
#pragma unroll
        for (int nt = 0; nt < 8; nt++) {
            int col = col0 + (warp_n << 6) + (nt << 3) + (tig << 1);
            float bx = bias[col], by = bias[col + 1];
#pragma unroll
            for (int h = 0; h < 2; h++) {
                size_t row = (size_t)row0 + (warp_m << 5) + (mt << 4) + gid + (h << 3);
                *(__half2*)(C + row * DDIM + col) =
                    __floats2half2_rn(acc[mt][nt][2 * h] + bx,
                                      acc[mt][nt][2 * h + 1] + by);
            }
        }
    }
}

// Variant 2: output GEMM — fp32 out + resid (R15 kernel, single B).
__global__ __launch_bounds__(256) void h_gemmf_kernel(
    const __half* __restrict__ A, const __half* __restrict__ Bt,
    const float* __restrict__ bias, const float* __restrict__ resid,
    float* __restrict__ C)
{
    extern __shared__ __half hsm[];
    __half (*As)[128][40] = (__half(*)[128][40])hsm;
    __half (*Bs)[128][40] = (__half(*)[128][40])(hsm + 2 * 128 * 40);

    int tid = threadIdx.x;
    int lane = tid & 31, wid = tid >> 5;
    int warp_m = wid & 3, warp_n = wid >> 2;
    int gid = lane >> 2, tig = lane & 3;
    int row0 = blockIdx.y << 7, col0 = blockIdx.x << 7;

    float acc[2][8][4];
#pragma unroll
    for (int mt = 0; mt < 2; mt++)
#pragma unroll
        for (int nt = 0; nt < 8; nt++)
#pragma unroll
            for (int r = 0; r < 4; r++) acc[mt][nt][r] = 0.f;

    int rowS = tid >> 1, colS = (tid & 1) << 4;
    const __half* Ag = A + (size_t)(row0 + rowS) * DDIM + colS;
    const __half* Bg = Bt + (size_t)(col0 + rowS) * DDIM + colS;

    cp_async16(&As[0][rowS][colS], Ag);
    cp_async16(&As[0][rowS][colS + 8], Ag + 8);
    cp_async16(&Bs[0][rowS][colS], Bg);
    cp_async16(&Bs[0][rowS][colS + 8], Bg + 8);
    cp_commit(); cp_wait_all(); __syncthreads();

    for (int t = 0; t < 32; t++) {
        if (t < 31) {
            int sn = (t + 1) & 1, k0n = (t + 1) << 5;
            cp_async16(&As[sn][rowS][colS], Ag + k0n);
            cp_async16(&As[sn][rowS][colS + 8], Ag + k0n + 8);
            cp_async16(&Bs[sn][rowS][colS], Bg + k0n);
            cp_async16(&Bs[sn][rowS][colS + 8], Bg + k0n + 8);
            cp_commit();
        }
        int s = t & 1;
#pragma unroll
        for (int ks = 0; ks < 2; ks++) {
            int kk = ks << 4;
            uint32_t af[2][4];
            int mrow = (warp_m << 5) + gid;
#pragma unroll
            for (int mt = 0; mt < 2; mt++) {
                int r = mrow + (mt << 4);
                af[mt][0] = *(const uint32_t*)&As[s][r][kk + (tig << 1)];
                af[mt][1] = *(const uint32_t*)&As[s][r + 8][kk + (tig << 1)];
                af[mt][2] = *(const uint32_t*)&As[s][r][kk + (tig << 1) + 8];
                af[mt][3] = *(const uint32_t*)&As[s][r + 8][kk + (tig << 1) + 8];
            }
            uint32_t bf[8][2];
            int nbase = (warp_n << 6) + gid;
#pragma unroll
            for (int nt = 0; nt < 8; nt++) {
                int c = nbase + (nt << 3);
                bf[nt][0] = *(const uint32_t*)&Bs[s][c][kk + (tig << 1)];
                bf[nt][1] = *(const uint32_t*)&Bs[s][c][kk + (tig << 1) + 8];
            }
#pragma unroll
            for (int mt = 0; mt < 2; mt++)
#pragma unroll
                for (int nt = 0; nt < 8; nt++)
                    mma_f16(acc[mt][nt][0], acc[mt][nt][1],
                            acc[mt][nt][2], acc[mt][nt][3],
                            af[mt][0], af[mt][1], af[mt][2], af[mt][3],
                            bf[nt][0], bf[nt][1]);
        }
        cp_wait_all(); __syncthreads();
    }

#pragma unroll
    for (int mt = 0; mt < 2; mt++) {
#pragma unroll
        for (int nt = 0; nt < 8; nt++) {
            int col = col0 + (warp_n << 6) + (nt << 3) + (tig << 1);
            float bx = bias[col], by = bias[col + 1];
#pragma unroll
            for (int h = 0; h < 2; h++) {
                size_t row = (size_t)row0 + (warp_m << 5) + (mt << 4) + gid + (h << 3);
                float2 rv = *(const float2*)(resid + row * DDIM + col);
                float2 o;
                o.x = acc[mt][nt][2 * h + 0] + bx + rv.x;
                o.y = acc[mt][nt][2 * h + 1] + by + rv.y;
                *(float2*)(C + row * DDIM + col) = o;
            }
        }
    }
}

// ---------------------------------------------------------------------------
// FP16 tensor-core windowed attention, 32 q-rows per block, 2 CTAs/SM.
// 16 warps: warp w -> n-tile (w&7), m-tile mg=(w>>3).
// QK^T and PV via m16n8k16 fp16 mma; softmax fp32 in Ssm, P stored half
// in-place; ctx written half into g_xh.
// Smem: Ssm[32][516]f32 + KVh[2][64][72]half = 84480 B.
// ---------------------------------------------------------------------------
#define SS_LD 516
#define KV_LDH 72
#define ATTN_SMEM_BYTES (32 * SS_LD * 4 + 2 * 64 * KV_LDH * 2)

__global__ __launch_bounds__(512, 2) void attn_h_kernel(
    const __half* __restrict__ Qh, const __half* __restrict__ Kh,
    const __half* __restrict__ Vh, __half* __restrict__ ctx)
{
    extern __shared__ float sm[];
    float* Ssm = sm;                               // [32][516] fp32
    __half* KV0 = (__half*)(sm + 32 * SS_LD);      // [64][72] half
    __half* KV1 = KV0 + 64 * KV_LDH;               // [64][72] half (Q overlay)

    int tid = threadIdx.x;
    int lane = tid & 31;
    int w = tid >> 5;
    int gid = lane >> 2, tig = lane & 3;
    int nt = w & 7;
    int mg = w >> 3;
    int mrow = mg << 4;

    int hid = blockIdx.y;                   // (b, win, h)
    int b = hid >> 7;
    int wn = (hid >> 4) & 7;
    int h = hid & 15;
    int t0 = b * 4096 + wn * 512;
    int hcol = h << 6;
    int qbase = blockIdx.x << 5;            // 32 q-rows per block

    int r = tid >> 3;                       // 0..63 KV staging row
    int c0 = (tid & 7) << 3;                // 0..56 staging col (8 halves=16B)

    // ---- stage Q (32x64 half) into KV1 + prefetch K tile 0 into KV0 ----
    {
        int qr = tid >> 4;                  // 0..31
        int qc = (tid & 15) << 2;           // 0..60 halves (8B chunks)
        uint2 qv = *(const uint2*)(Qh + (size_t)(t0 + qbase + qr) * DDIM + hcol + qc);
        cp_async16(&KV0[r * KV_LDH + c0],
                   Kh + (size_t)(t0 + r) * DDIM + hcol + c0);
        cp_commit();
        *(uint2*)&KV1[qr * KV_LDH + qc] = qv;
    }
    __syncthreads();                        // Q visible

    // ---- hoist Q A-fragments (fp16, 4 k-steps of 16) ----
    uint32_t af[4][4];
#pragma unroll
    for (int ks = 0; ks < 4; ks++) {
        int kk = ks << 4;
        af[ks][0] = *(const uint32_t*)&KV1[(mrow + gid) * KV_LDH + kk + (tig << 1)];
        af[ks][1] = *(const uint32_t*)&KV1[(mrow + gid + 8) * KV_LDH + kk + (tig << 1)];
        af[ks][2] = *(const uint32_t*)&KV1[(mrow + gid) * KV_LDH + kk + (tig << 1) + 8];
        af[ks][3] = *(const uint32_t*)&KV1[(mrow + gid + 8) * KV_LDH + kk + (tig << 1) + 8];
    }
    cp_wait_all();
    __syncthreads();                        // af done (KV1 free), K0 visible

    // ---- scores S[32][512] = Q K^T, pipelined over 8 key tiles ----
    for (int kt = 0; kt < 8; kt++) {
        __half* cur = (kt & 1) ? KV1 : KV0;
        if (kt < 7) {
            __half* nxt = (kt & 1) ? KV0 : KV1;
            cp_async16(&nxt[r * KV_LDH + c0],
                       Kh + (size_t)(t0 + (kt + 1) * 64 + r) * DDIM + hcol + c0);
            cp_commit();
        }
        float s0 = 0.f, s1 = 0.f, s2 = 0.f, s3 = 0.f;
#pragma unroll
        for (int ks = 0; ks < 4; ks++) {
            int kk = ks << 4;
            uint32_t b0 = *(const uint32_t*)&cur[((nt << 3) + gid) * KV_LDH + kk + (tig << 1)];
            uint32_t b1 = *(const uint32_t*)&cur[((nt << 3) + gid) * KV_LDH + kk + (tig << 1) + 8];
            mma_f16(s0, s1, s2, s3,
                    af[ks][0], af[ks][1], af[ks][2], af[ks][3], b0, b1);
        }
        {
            int row = mrow + gid;
            int col = kt * 64 + (nt << 3) + (tig << 1);
            *(float2*)&Ssm[row * SS_LD + col] = make_float2(s0, s1);
            *(float2*)&Ssm[(row + 8) * SS_LD + col] = make_float2(s2, s3);
        }
        cp_wait_all();
        __syncthreads();
    }

    // prefetch V tile 0 into KV0, overlaps softmax
    cp_async16(&KV0[r * KV_LDH + c0],
               Vh + (size_t)(t0 + r) * DDIM + hcol + c0);
    cp_commit();

    // ---- softmax (fp32), write P in-place as half ----
    {
#pragma unroll
        for (int q = 0; q < 2; q++) {
            int rr = (w << 1) + q;
            float vals[16];
            float m = -1e30f;
#pragma unroll
            for (int t = 0; t < 16; t++) {
                vals[t] = Ssm[rr * SS_LD + lane + 32 * t];
                m = fmaxf(m, vals[t]);
            }
#pragma unroll
            for (int off = 16; off > 0; off >>= 1)
                m = fmaxf(m, __shfl_xor_sync(0xffffffffu, m, off));
            float s = 0.f;
#pragma unroll
            for (int t = 0; t < 16; t++) {
                float e = __expf((vals[t] - m) * 0.125f);
                vals[t] = e;
                s += e;
            }
#pragma unroll
            for (int off = 16; off > 0; off >>= 1)
                s += __shfl_xor_sync(0xffffffffu, s, off);
            float inv = 1.0f / s;
            // warp-synchronous: all reads above done before these writes
            __half* pr = (__half*)&Ssm[rr * SS_LD];
#pragma unroll
            for (int t = 0; t < 16; t++)
                pr[lane + 32 * t] = __float2half(vals[t] * inv);
        }
    }
    cp_wait_all();
    __syncthreads();   // V0 ready; P writes visible

    // ---- O[32][64] = P[32][512] @ V[512][64] (fp16), pipelined ----
    float o0 = 0.f, o1 = 0.f, o2 = 0.f, o3 = 0.f;

    for (int kt = 0; kt < 8; kt++) {
        __half* cur = (kt & 1) ? KV1 : KV0;
        if (kt < 7) {
            __half* nxt = (kt & 1) ? KV0 : KV1;
            cp_async16(&nxt[r * KV_LDH + c0],
                       Vh + (size_t)(t0 + (kt + 1) * 64 + r) * DDIM + hcol + c0);
            cp_commit();
        }
        const __half* p0 = (const __half*)&Ssm[(mrow + gid) * SS_LD];
        const __half* p1 = (const __half*)&Ssm[(mrow + gid + 8) * SS_LD];
        int nn = (nt << 3) + gid;
#pragma unroll
        for (int ks = 0; ks < 4; ks++) {
            int kk = ks << 4;               // local key base
            int kc = kt * 64 + kk;
            uint32_t a0 = *(const uint32_t*)&p0[kc + (tig << 1)];
            uint32_t a1 = *(const uint32_t*)&p1[kc + (tig << 1)];
            uint32_t a2 = *(const uint32_t*)&p0[kc + (tig << 1) + 8];
            uint32_t a3 = *(const uint32_t*)&p1[kc + (tig << 1) + 8];
            uint32_t b0 = pack_h2(cur[(kk + (tig << 1)) * KV_LDH + nn],
                                  cur[(kk + (tig << 1) + 1) * KV_LDH + nn]);
            uint32_t b1 = pack_h2(cur[(kk + (tig << 1) + 8) * KV_LDH + nn],
                                  cur[(kk + (tig << 1) + 9) * KV_LDH + nn]);
            mma_f16(o0, o1, o2, o3, a0, a1, a2, a3, b0, b1);
        }
        cp_wait_all();
        __syncthreads();
    }

    // ---- store ctx as half ----
    {
        size_t row = (size_t)t0 + qbase + mrow + gid;
        int col = hcol + (nt << 3) + (tig << 1);
        *(__half2*)(ctx + row * DDIM + col) = __floats2half2_rn(o0, o1);
        *(__half2*)(ctx + (row + 8) * DDIM + col) = __floats2half2_rn(o2, o3);
    }
}

// ---------------------------------------------------------------------------
// LayerNorm per row (1024 elems), keras eps = 1e-3. One block per row.
// ---------------------------------------------------------------------------
__global__ __launch_bounds__(256) void ln_kernel(
    const float* __restrict__ Y, const float* __restrict__ gamma,
    const float* __restrict__ beta, float* __restrict__ out)
{
    int row = blockIdx.x;
    int tid = threadIdx.x;
    const float* y = Y + (size_t)row * DDIM;

    float4 v = *(const float4*)(y + tid * 4);
    float s  = v.x + v.y + v.z + v.w;
    float sq = v.x * v.x + v.y * v.y + v.z * v.z + v.w * v.w;

#pragma unroll
    for (int off = 16; off > 0; off >>= 1) {
        s  += __shfl_xor_sync(0xffffffffu, s, off);
        sq += __shfl_xor_sync(0xffffffffu, sq, off);
    }
    __shared__ float ss[8], ssq[8];
    int lane = tid & 31, wid = tid >> 5;
    if (lane == 0) { ss[wid] = s; ssq[wid] = sq; }
    __syncthreads();
    float S = 0.f, SQ = 0.f;
#pragma unroll
    for (int i = 0; i < 8; i++) { S += ss[i]; SQ += ssq[i]; }

    float mu  = S * (1.0f / 1024.0f);
    float var = SQ * (1.0f / 1024.0f) - mu * mu;
    float inv = rsqrtf(var + 1e-3f);

    float4 g  = *(const float4*)(gamma + tid * 4);
    float4 be = *(const float4*)(beta + tid * 4);
    float4 o;
    o.x = (v.x - mu) * inv * g.x + be.x;
    o.y = (v.y - mu) * inv * g.y + be.y;
    o.z = (v.z - mu) * inv * g.z + be.z;
    o.w = (v.w - mu) * inv * g.w + be.w;
    *(float4*)(out + (size_t)row * DDIM + tid * 4) = o;
}

// ---------------------------------------------------------------------------
extern "C" void kernel_launch(void* const* d_in, const int* in_sizes, int n_in,
                              void* d_out, int out_size)
{
    const float* x     = (const float*)d_in[0];
    const float* Wq    = (const float*)d_in[1];
    const float* bq    = (const float*)d_in[2];
    const float* Wk    = (const float*)d_in[3];
    const float* bk    = (const float*)d_in[4];
    const float* Wv    = (const float*)d_in[5];
    const float* bv    = (const float*)d_in[6];
    const float* Wo    = (const float*)d_in[7];
    const float* bo    = (const float*)d_in[8];
    const float* gamma = (const float*)d_in[9];
    const float* beta  = (const float*)d_in[10];
    float* out = (float*)d_out;
    (void)in_sizes; (void)n_in; (void)out_size;

    __half *Qhp, *Khp, *Vhp, *xhp, *Whp;
    float* Yp;
    cudaGetSymbolAddress((void**)&Qhp, g_Qh);
    cudaGetSymbolAddress((void**)&Khp, g_Kh);
    cudaGetSymbolAddress((void**)&Vhp, g_Vh);
    cudaGetSymbolAddress((void**)&xhp, g_xh);
    cudaGetSymbolAddress((void**)&Yp,  g_Y);
    cudaGetSymbolAddress((void**)&Whp, g_Wh);

    cudaFuncSetAttribute(h_gemm3h_kernel,
                         cudaFuncAttributeMaxDynamicSharedMemorySize, GEMM_SMEM_BYTES);
    cudaFuncSetAttribute(h_gemmf_kernel,
                         cudaFuncAttributeMaxDynamicSharedMemorySize, GEMM_SMEM_BYTES);
    cudaFuncSetAttribute(attn_h_kernel,
                         cudaFuncAttributeMaxDynamicSharedMemorySize, ATTN_SMEM_BYTES);

    const size_t WSZ = (size_t)DDIM * DDIM;

    // prep: weights -> half [n][k]; x -> half
    wcvt_kernel<<<dim3(32, 32, 4), 256>>>(Wq, Wk, Wv, Wo, Whp);
    f2h_kernel<<<16384, 256>>>(x, xhp);

    // Q, K, V (half outputs) in one launch
    h_gemm3h_kernel<<<dim3(8, 128, 3), 256, GEMM_SMEM_BYTES>>>(
        xhp, Whp, Whp + WSZ, Whp + 2 * WSZ, bq, bk, bv, Qhp, Khp, Vhp);

    // attention: fp16 end-to-end; ctx written half into g_xh (x-half dead)
    attn_h_kernel<<<dim3(16, 512), 512, ATTN_SMEM_BYTES>>>(Qhp, Khp, Vhp, xhp);

    // Y = ctx @ Wo + bo + x  (fp32 out)
    h_gemmf_kernel<<<dim3(8, 128), 256, GEMM_SMEM_BYTES>>>(
        xhp, Whp + 3 * WSZ, bo, x, Yp);

    ln_kernel<<<M_TOK, 256>>>(Yp, gamma, beta, out);
}